// round 1
// baseline (speedup 1.0000x reference)
#include <cuda_runtime.h>
#include <cstdint>

// Problem constants (from reference): N=200000 nodes, D=256 features, G=512 graphs.
#define D 256
#define G 512
#define MAX_N 262144          // >= 200000, headroom
#define MAX_NB 1024           // >= ceil(N/256)

// Scratch (device globals — no allocation allowed)
__device__ int   g_idx[MAX_N];          // normalized int32 batch indices
__device__ int   g_flags[MAX_NB];       // per-block detect flags (bit0: odd-word nonzero, bit1: even-word nonzero)
__device__ float g_sum[G * D];          // segment sums
__device__ float g_hG[G * D];           // relu(sum @ W + b)

// ---------------------------------------------------------------------------
// Kernel 1: detect whether batch_idx buffer is int64 or int32.
// View the buffer as int32 words [0, n). For little-endian int64 values in
// [0, 512), every odd word is 0. For sorted int32 data, the tail odd words
// hold values near 511 (nonzero). Write per-block flags (overwrite, so no
// reset needed across graph replays).
// ---------------------------------------------------------------------------
__global__ void k_detect(const int* __restrict__ raw, int n)
{
    int i = blockIdx.x * blockDim.x + threadIdx.x;
    int odd_nz = 0, even_nz = 0;
    if (i < n) {
        int v = raw[i];
        if (v != 0) {
            if (i & 1) odd_nz = 1; else even_nz = 1;
        }
    }
    int o = __syncthreads_or(odd_nz);
    int e = __syncthreads_or(even_nz);
    if (threadIdx.x == 0) g_flags[blockIdx.x] = o | (e << 1);
}

// ---------------------------------------------------------------------------
// Kernel 2: reduce flags, convert indices to int32, zero segment accumulator.
// ---------------------------------------------------------------------------
__global__ void k_convert(const int* __restrict__ raw, int n, int nb)
{
    // reduce detect flags (nb <= 1024, cheap)
    int f = 0;
    for (int j = threadIdx.x; j < nb; j += blockDim.x) f |= g_flags[j];
    f = __syncthreads_or(f);
    int any_odd  = f & 1;
    int any_even = (f >> 1) & 1;

    int i = blockIdx.x * blockDim.x + threadIdx.x;
    if (i < n) {
        int v;
        if (any_odd)            v = raw[i];        // genuine int32 data
        else if (any_even)      v = raw[2 * i];    // int64 data, take low word
        else                    v = 0;             // all zero, either way
        g_idx[i] = v;
    }
    if (i < G * D) g_sum[i] = 0.0f;
}

// ---------------------------------------------------------------------------
// Kernel 3: segment sum, exploiting sorted batch_idx.
// Block handles 256 contiguous rows. 256 threads = 4 row-stripes x 64
// column-quads (float4). Register accumulation, atomic flush only on
// segment change (~2 segments per block on average).
// ---------------------------------------------------------------------------
__global__ void k_segsum(const float* __restrict__ h, int n)
{
    __shared__ int sidx[256];
    int r0 = blockIdx.x * 256;
    {
        int r = r0 + threadIdx.x;
        sidx[threadIdx.x] = (r < n) ? g_idx[r] : -1;
    }
    __syncthreads();

    int tx = threadIdx.x & 63;   // column quad
    int ty = threadIdx.x >> 6;   // row stripe (0..3), uniform per warp

    float4 acc = make_float4(0.f, 0.f, 0.f, 0.f);
    int cur = -1;

    for (int rr = ty; rr < 256; rr += 4) {
        int row = r0 + rr;
        if (row >= n) break;
        int seg = sidx[rr];
        if (seg != cur) {
            if (cur >= 0) {
                float* dst = &g_sum[cur * D + tx * 4];
                atomicAdd(dst + 0, acc.x);
                atomicAdd(dst + 1, acc.y);
                atomicAdd(dst + 2, acc.z);
                atomicAdd(dst + 3, acc.w);
            }
            acc = make_float4(0.f, 0.f, 0.f, 0.f);
            cur = seg;
        }
        const float4 v = *reinterpret_cast<const float4*>(h + (size_t)row * D + tx * 4);
        acc.x += v.x; acc.y += v.y; acc.z += v.z; acc.w += v.w;
    }
    if (cur >= 0) {
        float* dst = &g_sum[cur * D + tx * 4];
        atomicAdd(dst + 0, acc.x);
        atomicAdd(dst + 1, acc.y);
        atomicAdd(dst + 2, acc.z);
        atomicAdd(dst + 3, acc.w);
    }
}

// ---------------------------------------------------------------------------
// Kernel 4: h_G = relu(sum @ W + b). One block per graph row.
// W is 256 KB -> L2-resident after first touch.
// ---------------------------------------------------------------------------
__global__ void k_gemm(const float* __restrict__ W, const float* __restrict__ b)
{
    __shared__ float srow[D];
    int g = blockIdx.x;
    int t = threadIdx.x;
    srow[t] = g_sum[g * D + t];
    __syncthreads();

    float acc = b[t];
#pragma unroll 8
    for (int k = 0; k < D; k++) {
        acc += srow[k] * W[k * D + t];
    }
    g_hG[g * D + t] = fmaxf(acc, 0.0f);
}

// ---------------------------------------------------------------------------
// Kernel 5: out = h_G[batch_idx] + h  (float4 streaming; h_G L2-resident)
// ---------------------------------------------------------------------------
__global__ void k_out(const float* __restrict__ h, float* __restrict__ out, int n)
{
    int gt = blockIdx.x * blockDim.x + threadIdx.x; // one thread per float4
    int i = gt >> 6;        // row
    int q = gt & 63;        // column quad
    if (i >= n) return;
    int seg = g_idx[i];
    const float4 a = *reinterpret_cast<const float4*>(h + (size_t)i * D + q * 4);
    const float4 v = *reinterpret_cast<const float4*>(g_hG + seg * D + q * 4);
    float4 r;
    r.x = a.x + v.x; r.y = a.y + v.y; r.z = a.z + v.z; r.w = a.w + v.w;
    *reinterpret_cast<float4*>(out + (size_t)i * D + q * 4) = r;
}

extern "C" void kernel_launch(void* const* d_in, const int* in_sizes, int n_in,
                              void* d_out, int out_size)
{
    const float* h   = (const float*)d_in[0];
    const int*   raw = (const int*)  d_in[1];   // int32 view of batch_idx (may be int64 storage)
    const float* W   = (const float*)d_in[2];
    const float* b   = (const float*)d_in[3];
    float* out = (float*)d_out;

    const int n  = in_sizes[1];             // number of nodes (element count of batch_idx)
    const int nb = (n + 255) / 256;

    k_detect <<<nb, 256>>>(raw, n);
    k_convert<<<nb, 256>>>(raw, n, nb);
    k_segsum <<<nb, 256>>>(h, n);
    k_gemm   <<<G, 256>>>(W, b);
    {
        long long tq = (long long)n * 64;   // one thread per float4
        int blocks = (int)((tq + 255) / 256);
        k_out<<<blocks, 256>>>(h, out, n);
    }
}